// round 5
// baseline (speedup 1.0000x reference)
#include <cuda_runtime.h>
#include <math.h>

#define NN 2048
#define BB 8

// ---------------- scratch (static device allocations) ----------------
__device__ float g_PL[BB * 15 * NN];                 // left projections  [b][ct][row]
__device__ float g_PRpart[32 * BB * 15 * NN];        // right projection partials per h-chunk
__device__ float g_PR[BB * 15 * NN];                 // right projections [b][ct][col]
__device__ float g_LR[BB * 2 * NN];                  // sigmoid outputs: [b][0]=left, [b][1]=right
__device__ float g_dsum[64 * BB];                    // per-(d,b) band sums

// ---------------- kernel 1: left projections ----------------
// PL[b][c*3+t][i] = sum_w x[b,i,w] * wl[c,t,w]
__global__ __launch_bounds__(256) void pl_kernel(const float* __restrict__ x,
                                                 const float* __restrict__ wl) {
    __shared__ float sw[15 * 128];
    int tid = threadIdx.x;
    int warp = tid >> 5, lane = tid & 31;
    int g = blockIdx.x * 8 + warp;          // 0..4095
    int b = g >> 9;                         // 512 warps per batch (2048/4 rows)
    int r0 = (g & 511) << 2;
    const float* xb = x + (size_t)b * NN * NN + (size_t)r0 * NN;

    float acc[4][15];
#pragma unroll
    for (int r = 0; r < 4; r++)
#pragma unroll
        for (int c = 0; c < 15; c++) acc[r][c] = 0.f;

    const float4* wl4 = (const float4*)wl;
    float4* sw4 = (float4*)sw;

#pragma unroll 1
    for (int k = 0; k < 16; ++k) {
        __syncthreads();
        for (int i = tid; i < 480; i += 256) {
            int ct = i >> 5, j = i & 31;
            sw4[ct * 32 + j] = wl4[ct * 512 + k * 32 + j];
        }
        __syncthreads();
        int w = k * 128 + lane * 4;
        float4 xv0 = *(const float4*)(xb + 0 * NN + w);
        float4 xv1 = *(const float4*)(xb + 1 * NN + w);
        float4 xv2 = *(const float4*)(xb + 2 * NN + w);
        float4 xv3 = *(const float4*)(xb + 3 * NN + w);
#pragma unroll
        for (int ct = 0; ct < 15; ++ct) {
            float4 wv = sw4[ct * 32 + lane];
            acc[0][ct] = fmaf(xv0.x, wv.x, acc[0][ct]);
            acc[0][ct] = fmaf(xv0.y, wv.y, acc[0][ct]);
            acc[0][ct] = fmaf(xv0.z, wv.z, acc[0][ct]);
            acc[0][ct] = fmaf(xv0.w, wv.w, acc[0][ct]);
            acc[1][ct] = fmaf(xv1.x, wv.x, acc[1][ct]);
            acc[1][ct] = fmaf(xv1.y, wv.y, acc[1][ct]);
            acc[1][ct] = fmaf(xv1.z, wv.z, acc[1][ct]);
            acc[1][ct] = fmaf(xv1.w, wv.w, acc[1][ct]);
            acc[2][ct] = fmaf(xv2.x, wv.x, acc[2][ct]);
            acc[2][ct] = fmaf(xv2.y, wv.y, acc[2][ct]);
            acc[2][ct] = fmaf(xv2.z, wv.z, acc[2][ct]);
            acc[2][ct] = fmaf(xv2.w, wv.w, acc[2][ct]);
            acc[3][ct] = fmaf(xv3.x, wv.x, acc[3][ct]);
            acc[3][ct] = fmaf(xv3.y, wv.y, acc[3][ct]);
            acc[3][ct] = fmaf(xv3.z, wv.z, acc[3][ct]);
            acc[3][ct] = fmaf(xv3.w, wv.w, acc[3][ct]);
        }
    }

#pragma unroll
    for (int r = 0; r < 4; r++) {
#pragma unroll
        for (int ct = 0; ct < 15; ++ct) {
            float v = acc[r][ct];
            v += __shfl_down_sync(0xffffffffu, v, 16);
            v += __shfl_down_sync(0xffffffffu, v, 8);
            v += __shfl_down_sync(0xffffffffu, v, 4);
            v += __shfl_down_sync(0xffffffffu, v, 2);
            v += __shfl_down_sync(0xffffffffu, v, 1);
            if (lane == 0) g_PL[((size_t)b * 15 + ct) * NN + r0 + r] = v;
        }
    }
}

// ---------------- kernel 2: right projection partials ----------------
// PR[b][c*3+t][j] = sum_h x[b,h,j] * wr[c,h,t]   (split over 32 h-chunks of 64)
__global__ __launch_bounds__(256) void prpart_kernel(const float* __restrict__ x,
                                                     const float* __restrict__ wr) {
    __shared__ float ws[64][16];
    int tid = threadIdx.x;
    int bx = blockIdx.x;
    int hc = bx & 31, half = (bx >> 5) & 1, b = bx >> 6;
    int h0 = hc * 64;

    for (int i = tid; i < 64 * 15; i += 256) {
        int hl = i / 15, ct = i % 15;
        int c = ct / 3, t = ct % 3;
        ws[hl][ct] = wr[((size_t)c * NN + (h0 + hl)) * 3 + t];
    }
    __syncthreads();

    int warp = tid >> 5, lane = tid & 31;
    int col0 = (half * 8 + warp) * 128 + lane * 4;
    const float* xb = x + (size_t)b * NN * NN;

    float4 acc[15];
#pragma unroll
    for (int ct = 0; ct < 15; ++ct) acc[ct] = make_float4(0.f, 0.f, 0.f, 0.f);

#pragma unroll 1
    for (int hl = 0; hl < 64; ++hl) {
        float4 xv = *(const float4*)(xb + (size_t)(h0 + hl) * NN + col0);
#pragma unroll
        for (int ct = 0; ct < 15; ++ct) {
            float wv = ws[hl][ct];
            acc[ct].x = fmaf(xv.x, wv, acc[ct].x);
            acc[ct].y = fmaf(xv.y, wv, acc[ct].y);
            acc[ct].z = fmaf(xv.z, wv, acc[ct].z);
            acc[ct].w = fmaf(xv.w, wv, acc[ct].w);
        }
    }

    float* dst = g_PRpart + (size_t)hc * (BB * 15 * NN);
#pragma unroll
    for (int ct = 0; ct < 15; ++ct)
        *(float4*)(dst + ((size_t)b * 15 + ct) * NN + col0) = acc[ct];
}

// ---------------- kernel 3: reduce partials ----------------
__global__ __launch_bounds__(256) void prreduce_kernel() {
    int i = blockIdx.x * 256 + threadIdx.x;   // 0 .. 245759
    float s = 0.f;
#pragma unroll
    for (int hc = 0; hc < 32; ++hc) s += g_PRpart[(size_t)hc * (BB * 15 * NN) + i];
    g_PR[i] = s;
}

// ---------------- kernel 4: fused conv stack + sigmoid ----------------
#define TW 512
#define HALO 6
#define W2 (TW + 2 * HALO)    // 524
__global__ __launch_bounds__(256) void conv_kernel(
    const float* __restrict__ bl, const float* __restrict__ br,
    const float* __restrict__ wA, const float* __restrict__ bA,
    const float* __restrict__ wB, const float* __restrict__ bB,
    const float* __restrict__ wT, const float* __restrict__ bT,
    const float* __restrict__ wm, const float* __restrict__ bm) {
    __shared__ float hbuf[2][10][W2];
    __shared__ float sA[300], sB[300], sT[300];
    __shared__ float swm[20], sbA[10], sbB[10], sbT[10], sbm[2];

    int tid = threadIdx.x;
    int b = blockIdx.x >> 2;
    int p0 = (blockIdx.x & 3) * TW;

    for (int i = tid; i < 300; i += 256) {
        sA[i] = wA[i];
        sB[i] = wB[i];
        int o = i / 30, ii = (i / 3) % 10, t = i % 3;
        sT[i] = wT[(ii * 10 + o) * 3 + (2 - t)];   // wTc[o][ii][t] = wT[ii][o][2-t]
    }
    if (tid < 20) swm[tid] = wm[tid];
    if (tid < 10) { sbA[tid] = bA[tid]; sbB[tid] = bB[tid]; sbT[tid] = bT[tid]; }
    if (tid < 2) sbm[tid] = bm[tid];

    // build lr (with halo) from projections + 3-tap shift + bias
    for (int i = tid; i < 10 * W2; i += 256) {
        int ch = i / W2, pl = i % W2;
        int gp = p0 - HALO + pl;
        float v = 0.f;
        if (gp >= 0 && gp < NN) {
            if (ch < 5) {
                v = bl[ch];
#pragma unroll
                for (int t = 0; t < 3; t++) {
                    int ri = gp - 1 + t;
                    if (ri >= 0 && ri < NN) v += g_PL[((size_t)b * 15 + ch * 3 + t) * NN + ri];
                }
            } else {
                int c = ch - 5;
                v = br[c];
#pragma unroll
                for (int t = 0; t < 3; t++) {
                    int ci = gp - 1 + t;
                    if (ci >= 0 && ci < NN) v += g_PR[((size_t)b * 15 + c * 3 + t) * NN + ci];
                }
            }
        }
        hbuf[0][ch][pl] = v;
    }
    __syncthreads();

    int src = 0;
#pragma unroll 1
    for (int layer = 0; layer < 6; ++layer) {
        const float* W = (layer == 0) ? sA : ((layer < 3) ? sB : sT);
        const float* bias = (layer == 0) ? sbA : ((layer < 3) ? sbB : sbT);
        int dst = src ^ 1;
        for (int i = tid; i < 10 * W2; i += 256) {
            int o = i / W2, p = i % W2;
            float s = bias[o];
#pragma unroll
            for (int ci = 0; ci < 10; ++ci) {
                float a0 = (p > 0) ? hbuf[src][ci][p - 1] : 0.f;
                float a1 = hbuf[src][ci][p];
                float a2 = (p < W2 - 1) ? hbuf[src][ci][p + 1] : 0.f;
                const float* w3 = W + (o * 10 + ci) * 3;
                s = fmaf(a0, w3[0], s);
                s = fmaf(a1, w3[1], s);
                s = fmaf(a2, w3[2], s);
            }
            hbuf[dst][o][p] = fmaxf(s, 0.f);
        }
        __syncthreads();
        src = dst;
    }

    // pointwise wm + sigmoid -> left/right
    for (int i = tid; i < 2 * TW; i += 256) {
        int sch = i / TW;
        int pl = i % TW;
        int p = HALO + pl;
        float z = sbm[sch];
#pragma unroll
        for (int ci = 0; ci < 10; ++ci) z = fmaf(hbuf[src][ci][p], swm[sch * 10 + ci], z);
        g_LR[((size_t)b * 2 + sch) * NN + p0 + pl] = 1.f / (1.f + expf(-z));
    }
}

// ---------------- kernel 5: diagonal-band predictions (raw p + per-(d,b) sums) ----------------
__global__ __launch_bounds__(256) void preds_kernel(const float* __restrict__ x,
                                                    float* __restrict__ out) {
    __shared__ float red[8];
    int b = blockIdx.x >> 6;
    int d = (blockIdx.x & 63) + 1;
    int L = NN - d - 1;
    const float* xb = x + (size_t)b * NN * NN;
    const float* left = g_LR + (size_t)b * 2 * NN;
    const float* right = left + NN;
    int tid = threadIdx.x;

    size_t base = (size_t)b * 128928 + (size_t)(d - 1) * 2047 - (size_t)((d - 1) * d / 2);

    float lsum = 0.f;
    for (int j = tid; j < L; j += 256) {
        float c0 = expf(xb[(size_t)j * NN + j + d]);
        float c1 = expf(xb[(size_t)(j + 1) * NN + (j + 1) + d]);
        float mi = c1 * right[j + 1] + c0 * left[d + j];
        float mo = right[j] + left[d + 1 + j];
        float p = logf(mi / mo);
        out[base + j] = p;
        lsum += p;
    }
    lsum += __shfl_down_sync(0xffffffffu, lsum, 16);
    lsum += __shfl_down_sync(0xffffffffu, lsum, 8);
    lsum += __shfl_down_sync(0xffffffffu, lsum, 4);
    lsum += __shfl_down_sync(0xffffffffu, lsum, 2);
    lsum += __shfl_down_sync(0xffffffffu, lsum, 1);
    if ((tid & 31) == 0) red[tid >> 5] = lsum;
    __syncthreads();
    if (tid == 0) {
        float t = 0.f;
#pragma unroll
        for (int i = 0; i < 8; i++) t += red[i];
        g_dsum[(d - 1) * BB + b] = t;
    }
}

// ---------------- kernel 6: subtract global (over batches) mean per band ----------------
__global__ __launch_bounds__(256) void meansub_kernel(float* __restrict__ out) {
    int dd = blockIdx.x >> 3;          // 0..63
    int b = blockIdx.x & 7;
    int d = dd + 1;
    int L = NN - d - 1;
    float s = 0.f;
#pragma unroll
    for (int i = 0; i < 8; i++) s += g_dsum[dd * BB + i];
    float mean = s / (float)(BB * L);
    size_t base = (size_t)b * 128928 + (size_t)(d - 1) * 2047 - (size_t)((d - 1) * d / 2);
    for (int j = threadIdx.x; j < L; j += 256) out[base + j] -= mean;
}

// ---------------- launch ----------------
extern "C" void kernel_launch(void* const* d_in, const int* in_sizes, int n_in,
                              void* d_out, int out_size) {
    const float* x  = (const float*)d_in[0];
    const float* wl = (const float*)d_in[1];
    const float* bl = (const float*)d_in[2];
    const float* wr = (const float*)d_in[3];
    const float* br = (const float*)d_in[4];
    const float* wA = (const float*)d_in[5];
    const float* bA = (const float*)d_in[6];
    const float* wB = (const float*)d_in[7];
    const float* bB = (const float*)d_in[8];
    const float* wT = (const float*)d_in[9];
    const float* bT = (const float*)d_in[10];
    const float* wm = (const float*)d_in[11];
    const float* bm = (const float*)d_in[12];
    float* out = (float*)d_out;

    pl_kernel<<<512, 256>>>(x, wl);
    prpart_kernel<<<512, 256>>>(x, wr);
    prreduce_kernel<<<960, 256>>>();
    conv_kernel<<<32, 256>>>(bl, br, wA, bA, wB, bB, wT, bT, wm, bm);
    preds_kernel<<<512, 256>>>(x, out);
    meansub_kernel<<<512, 256>>>(out);
}

// round 6
// speedup vs baseline: 1.5286x; 1.5286x over previous
#include <cuda_runtime.h>
#include <math.h>

#define NN 2048
#define BB 8

// ---------------- scratch (static device allocations) ----------------
__device__ float g_PL[BB * 15 * NN];                 // left projections  [b][ct][row]
__device__ float g_PR[BB * 15 * NN];                 // right projections [b][ct][col]
__device__ float g_LR[BB * 2 * NN];                  // sigmoid outputs: [b][0]=left, [b][1]=right
__device__ float g_dsum[64 * BB];                    // per-(d,b) band sums

// ---------------- packed f32x2 helpers ----------------
__device__ __forceinline__ unsigned long long pack2(float lo, float hi) {
    unsigned long long r;
    asm("mov.b64 %0, {%1, %2};" : "=l"(r) : "f"(lo), "f"(hi));
    return r;
}
__device__ __forceinline__ void fma2(unsigned long long& d, unsigned long long a,
                                     unsigned long long b) {
    asm("fma.rn.f32x2 %0, %1, %2, %0;" : "+l"(d) : "l"(a), "l"(b));
}
__device__ __forceinline__ float hadd2(unsigned long long v) {
    float lo, hi;
    asm("mov.b64 {%0, %1}, %2;" : "=f"(lo), "=f"(hi) : "l"(v));
    return lo + hi;
}

// ---------------- kernel 1: left projections ----------------
// PL[b][c*3+t][i] = sum_w x[b,i,w] * wl[c,t,w]
__global__ __launch_bounds__(256) void pl_kernel(const float* __restrict__ x,
                                                 const float* __restrict__ wl) {
    __shared__ float sw[15 * 128];
    int tid = threadIdx.x;
    int warp = tid >> 5, lane = tid & 31;
    int g = blockIdx.x * 8 + warp;          // 0..4095
    int b = g >> 9;                         // 512 warps per batch (2048/4 rows)
    int r0 = (g & 511) << 2;
    const float* xb = x + (size_t)b * NN * NN + (size_t)r0 * NN;

    float acc[4][15];
#pragma unroll
    for (int r = 0; r < 4; r++)
#pragma unroll
        for (int c = 0; c < 15; c++) acc[r][c] = 0.f;

    const float4* wl4 = (const float4*)wl;
    float4* sw4 = (float4*)sw;

#pragma unroll 1
    for (int k = 0; k < 16; ++k) {
        __syncthreads();
        for (int i = tid; i < 480; i += 256) {
            int ct = i >> 5, j = i & 31;
            sw4[ct * 32 + j] = wl4[ct * 512 + k * 32 + j];
        }
        __syncthreads();
        int w = k * 128 + lane * 4;
        float4 xv0 = *(const float4*)(xb + 0 * NN + w);
        float4 xv1 = *(const float4*)(xb + 1 * NN + w);
        float4 xv2 = *(const float4*)(xb + 2 * NN + w);
        float4 xv3 = *(const float4*)(xb + 3 * NN + w);
#pragma unroll
        for (int ct = 0; ct < 15; ++ct) {
            float4 wv = sw4[ct * 32 + lane];
            acc[0][ct] = fmaf(xv0.x, wv.x, acc[0][ct]);
            acc[0][ct] = fmaf(xv0.y, wv.y, acc[0][ct]);
            acc[0][ct] = fmaf(xv0.z, wv.z, acc[0][ct]);
            acc[0][ct] = fmaf(xv0.w, wv.w, acc[0][ct]);
            acc[1][ct] = fmaf(xv1.x, wv.x, acc[1][ct]);
            acc[1][ct] = fmaf(xv1.y, wv.y, acc[1][ct]);
            acc[1][ct] = fmaf(xv1.z, wv.z, acc[1][ct]);
            acc[1][ct] = fmaf(xv1.w, wv.w, acc[1][ct]);
            acc[2][ct] = fmaf(xv2.x, wv.x, acc[2][ct]);
            acc[2][ct] = fmaf(xv2.y, wv.y, acc[2][ct]);
            acc[2][ct] = fmaf(xv2.z, wv.z, acc[2][ct]);
            acc[2][ct] = fmaf(xv2.w, wv.w, acc[2][ct]);
            acc[3][ct] = fmaf(xv3.x, wv.x, acc[3][ct]);
            acc[3][ct] = fmaf(xv3.y, wv.y, acc[3][ct]);
            acc[3][ct] = fmaf(xv3.z, wv.z, acc[3][ct]);
            acc[3][ct] = fmaf(xv3.w, wv.w, acc[3][ct]);
        }
    }

#pragma unroll
    for (int r = 0; r < 4; r++) {
#pragma unroll
        for (int ct = 0; ct < 15; ++ct) {
            float v = acc[r][ct];
            v += __shfl_down_sync(0xffffffffu, v, 16);
            v += __shfl_down_sync(0xffffffffu, v, 8);
            v += __shfl_down_sync(0xffffffffu, v, 4);
            v += __shfl_down_sync(0xffffffffu, v, 2);
            v += __shfl_down_sync(0xffffffffu, v, 1);
            if (lane == 0) g_PL[((size_t)b * 15 + ct) * NN + r0 + r] = v;
        }
    }
}

// ---------------- kernel 2: right projections, single pass, packed f32x2 ----------------
// PR[b][c*3+t][j] = sum_h x[b,h,j] * wr[c,h,t]
// Block = 64-col stripe, 256 threads = 64 cols x 4 h-segments (512 h each).
__global__ __launch_bounds__(256) void pr_kernel(const float* __restrict__ x,
                                                 const float* __restrict__ wr) {
    __shared__ float2 ws[4][32][15];     // seg, h-pair, ct   (15360 B)
    __shared__ float2 racc[3][64][15];   // reduce buffer     (23040 B)

    int tid = threadIdx.x;
    int b = blockIdx.x >> 5;
    int stripe = blockIdx.x & 31;
    int colloc = tid & 63;
    int seg = tid >> 6;                  // 0..3
    int col = stripe * 64 + colloc;
    const float* xb = x + (size_t)b * NN * NN + col;

    unsigned long long acc[15];
#pragma unroll
    for (int ct = 0; ct < 15; ++ct) acc[ct] = 0ull;

#pragma unroll 1
    for (int chunk = 0; chunk < 8; ++chunk) {
        __syncthreads();
        // stage packed weights: 4 segs x 32 h-pairs x 15 ct
        for (int i = tid; i < 1920; i += 256) {
            int s = i / 480, rem = i % 480;
            int hp = rem / 15, ct = rem % 15;
            int h = s * 512 + chunk * 64 + hp * 2;
            int c = ct / 3, t = ct % 3;
            ws[s][hp][ct] = make_float2(wr[((size_t)c * NN + h) * 3 + t],
                                        wr[((size_t)c * NN + h + 1) * 3 + t]);
        }
        __syncthreads();
        int hbase = seg * 512 + chunk * 64;
        const float* xp = xb + (size_t)hbase * NN;
#pragma unroll 4
        for (int hp = 0; hp < 32; ++hp) {
            float x0 = xp[(size_t)(2 * hp) * NN];
            float x1 = xp[(size_t)(2 * hp + 1) * NN];
            unsigned long long xv = pack2(x0, x1);
#pragma unroll
            for (int ct = 0; ct < 15; ++ct) {
                float2 w2 = ws[seg][hp][ct];
                fma2(acc[ct], xv, pack2(w2.x, w2.y));
            }
        }
    }

    __syncthreads();
    if (seg > 0) {
#pragma unroll
        for (int ct = 0; ct < 15; ++ct) {
            float lo, hi;
            asm("mov.b64 {%0, %1}, %2;" : "=f"(lo), "=f"(hi) : "l"(acc[ct]));
            racc[seg - 1][colloc][ct] = make_float2(lo, hi);
        }
    }
    __syncthreads();
    if (seg == 0) {
#pragma unroll
        for (int ct = 0; ct < 15; ++ct) {
            float v = hadd2(acc[ct]);
#pragma unroll
            for (int s = 0; s < 3; ++s) {
                float2 r = racc[s][colloc][ct];
                v += r.x + r.y;
            }
            g_PR[((size_t)b * 15 + ct) * NN + col] = v;
        }
    }
}

// ---------------- kernel 4: fused conv stack + sigmoid ----------------
#define TW 128
#define NT (NN / TW)          // 16 tiles
#define HALO 6
#define W2 (TW + 2 * HALO)    // 140
__global__ __launch_bounds__(256) void conv_kernel(
    const float* __restrict__ bl, const float* __restrict__ br,
    const float* __restrict__ wA, const float* __restrict__ bA,
    const float* __restrict__ wB, const float* __restrict__ bB,
    const float* __restrict__ wT, const float* __restrict__ bT,
    const float* __restrict__ wm, const float* __restrict__ bm) {
    __shared__ float hbuf[2][10][W2];
    __shared__ float sA[300], sB[300], sT[300];
    __shared__ float swm[20], sbA[10], sbB[10], sbT[10], sbm[2];

    int tid = threadIdx.x;
    int b = blockIdx.x / NT;
    int p0 = (blockIdx.x % NT) * TW;

    for (int i = tid; i < 300; i += 256) {
        sA[i] = wA[i];
        sB[i] = wB[i];
        int o = i / 30, ii = (i / 3) % 10, t = i % 3;
        sT[i] = wT[(ii * 10 + o) * 3 + (2 - t)];   // wTc[o][ii][t] = wT[ii][o][2-t]
    }
    if (tid < 20) swm[tid] = wm[tid];
    if (tid < 10) { sbA[tid] = bA[tid]; sbB[tid] = bB[tid]; sbT[tid] = bT[tid]; }
    if (tid < 2) sbm[tid] = bm[tid];

    // build lr (with halo) from projections + 3-tap shift + bias
    for (int i = tid; i < 10 * W2; i += 256) {
        int ch = i / W2, pl = i % W2;
        int gp = p0 - HALO + pl;
        float v = 0.f;
        if (gp >= 0 && gp < NN) {
            if (ch < 5) {
                v = bl[ch];
#pragma unroll
                for (int t = 0; t < 3; t++) {
                    int ri = gp - 1 + t;
                    if (ri >= 0 && ri < NN) v += g_PL[((size_t)b * 15 + ch * 3 + t) * NN + ri];
                }
            } else {
                int c = ch - 5;
                v = br[c];
#pragma unroll
                for (int t = 0; t < 3; t++) {
                    int ci = gp - 1 + t;
                    if (ci >= 0 && ci < NN) v += g_PR[((size_t)b * 15 + c * 3 + t) * NN + ci];
                }
            }
        }
        hbuf[0][ch][pl] = v;
    }
    __syncthreads();

    int src = 0;
#pragma unroll 1
    for (int layer = 0; layer < 6; ++layer) {
        const float* W = (layer == 0) ? sA : ((layer < 3) ? sB : sT);
        const float* bias = (layer == 0) ? sbA : ((layer < 3) ? sbB : sbT);
        int dst = src ^ 1;
        for (int i = tid; i < 10 * W2; i += 256) {
            int o = i / W2, p = i % W2;
            float s = bias[o];
#pragma unroll
            for (int ci = 0; ci < 10; ++ci) {
                float a0 = (p > 0) ? hbuf[src][ci][p - 1] : 0.f;
                float a1 = hbuf[src][ci][p];
                float a2 = (p < W2 - 1) ? hbuf[src][ci][p + 1] : 0.f;
                const float* w3 = W + (o * 10 + ci) * 3;
                s = fmaf(a0, w3[0], s);
                s = fmaf(a1, w3[1], s);
                s = fmaf(a2, w3[2], s);
            }
            hbuf[dst][o][p] = fmaxf(s, 0.f);
        }
        __syncthreads();
        src = dst;
    }

    // pointwise wm + sigmoid -> left/right
    for (int i = tid; i < 2 * TW; i += 256) {
        int sch = i / TW;
        int pl = i % TW;
        int p = HALO + pl;
        float z = sbm[sch];
#pragma unroll
        for (int ci = 0; ci < 10; ++ci) z = fmaf(hbuf[src][ci][p], swm[sch * 10 + ci], z);
        g_LR[((size_t)b * 2 + sch) * NN + p0 + pl] = 1.f / (1.f + expf(-z));
    }
}

// ---------------- kernel 5: diagonal-band predictions (raw p + per-(d,b) sums) ----------------
__global__ __launch_bounds__(256) void preds_kernel(const float* __restrict__ x,
                                                    float* __restrict__ out) {
    __shared__ float red[8];
    int b = blockIdx.x >> 6;
    int d = (blockIdx.x & 63) + 1;
    int L = NN - d - 1;
    const float* xb = x + (size_t)b * NN * NN;
    const float* left = g_LR + (size_t)b * 2 * NN;
    const float* right = left + NN;
    int tid = threadIdx.x;

    size_t base = (size_t)b * 128928 + (size_t)(d - 1) * 2047 - (size_t)((d - 1) * d / 2);

    float lsum = 0.f;
    for (int j = tid; j < L; j += 256) {
        float c0 = expf(xb[(size_t)j * NN + j + d]);
        float c1 = expf(xb[(size_t)(j + 1) * NN + (j + 1) + d]);
        float mi = c1 * right[j + 1] + c0 * left[d + j];
        float mo = right[j] + left[d + 1 + j];
        float p = logf(mi / mo);
        out[base + j] = p;
        lsum += p;
    }
    lsum += __shfl_down_sync(0xffffffffu, lsum, 16);
    lsum += __shfl_down_sync(0xffffffffu, lsum, 8);
    lsum += __shfl_down_sync(0xffffffffu, lsum, 4);
    lsum += __shfl_down_sync(0xffffffffu, lsum, 2);
    lsum += __shfl_down_sync(0xffffffffu, lsum, 1);
    if ((tid & 31) == 0) red[tid >> 5] = lsum;
    __syncthreads();
    if (tid == 0) {
        float t = 0.f;
#pragma unroll
        for (int i = 0; i < 8; i++) t += red[i];
        g_dsum[(d - 1) * BB + b] = t;
    }
}

// ---------------- kernel 6: subtract global (over batches) mean per band ----------------
__global__ __launch_bounds__(256) void meansub_kernel(float* __restrict__ out) {
    int dd = blockIdx.x >> 3;          // 0..63
    int b = blockIdx.x & 7;
    int d = dd + 1;
    int L = NN - d - 1;
    float s = 0.f;
#pragma unroll
    for (int i = 0; i < 8; i++) s += g_dsum[dd * BB + i];
    float mean = s / (float)(BB * L);
    size_t base = (size_t)b * 128928 + (size_t)(d - 1) * 2047 - (size_t)((d - 1) * d / 2);
    for (int j = threadIdx.x; j < L; j += 256) out[base + j] -= mean;
}

// ---------------- launch ----------------
extern "C" void kernel_launch(void* const* d_in, const int* in_sizes, int n_in,
                              void* d_out, int out_size) {
    const float* x  = (const float*)d_in[0];
    const float* wl = (const float*)d_in[1];
    const float* bl = (const float*)d_in[2];
    const float* wr = (const float*)d_in[3];
    const float* br = (const float*)d_in[4];
    const float* wA = (const float*)d_in[5];
    const float* bA = (const float*)d_in[6];
    const float* wB = (const float*)d_in[7];
    const float* bB = (const float*)d_in[8];
    const float* wT = (const float*)d_in[9];
    const float* bT = (const float*)d_in[10];
    const float* wm = (const float*)d_in[11];
    const float* bm = (const float*)d_in[12];
    float* out = (float*)d_out;

    pl_kernel<<<512, 256>>>(x, wl);
    pr_kernel<<<256, 256>>>(x, wr);
    conv_kernel<<<8 * NT, 256>>>(bl, br, wA, bA, wB, bB, wT, bT, wm, bm);
    preds_kernel<<<512, 256>>>(x, out);
    meansub_kernel<<<512, 256>>>(out);
}